// round 9
// baseline (speedup 1.0000x reference)
#include <cuda_runtime.h>

// Problem constants
#define BV   8        // views
#define CC   47       // channels
#define CP   48       // padded channels (12 float4)
#define FHh  60
#define FWw  80
#define HW   (FHh*FWw)        // 4800
#define DHh  240
#define DWw  320
#define NPTS 150000
#define PB   128      // points per block
#define THREADS 256

// Transposed features: (V, H, W, CP) for contiguous per-pixel channel runs.
__device__ __align__(16) float g_feats_t[BV * HW * CP];   // ~7.4 MB
__device__ float g_invpose[BV * 12];                       // rows 0..2 of pose^-1

// ---------------------------------------------------------------------------
// Kernel 1: invert the 8 poses (general 4x4 adjugate inverse).
// For these poses ([I | t]) the result is exactly [I | -t] (det = 1), matching
// the reference's f32 LU inverse bit-for-bit.
// ---------------------------------------------------------------------------
__global__ void prep_poses_kernel(const float* __restrict__ poses) {
    int v = threadIdx.x;
    if (v >= BV) return;
    float m[16];
#pragma unroll
    for (int i = 0; i < 16; i++) m[i] = poses[v * 16 + i];

    float inv[16];
    inv[0]  =  m[5]*m[10]*m[15] - m[5]*m[11]*m[14] - m[9]*m[6]*m[15] + m[9]*m[7]*m[14] + m[13]*m[6]*m[11] - m[13]*m[7]*m[10];
    inv[4]  = -m[4]*m[10]*m[15] + m[4]*m[11]*m[14] + m[8]*m[6]*m[15] - m[8]*m[7]*m[14] - m[12]*m[6]*m[11] + m[12]*m[7]*m[10];
    inv[8]  =  m[4]*m[9]*m[15]  - m[4]*m[11]*m[13] - m[8]*m[5]*m[15] + m[8]*m[7]*m[13] + m[12]*m[5]*m[11] - m[12]*m[7]*m[9];
    inv[12] = -m[4]*m[9]*m[14]  + m[4]*m[10]*m[13] + m[8]*m[5]*m[14] - m[8]*m[6]*m[13] - m[12]*m[5]*m[10] + m[12]*m[6]*m[9];
    inv[1]  = -m[1]*m[10]*m[15] + m[1]*m[11]*m[14] + m[9]*m[2]*m[15] - m[9]*m[3]*m[14] - m[13]*m[2]*m[11] + m[13]*m[3]*m[10];
    inv[5]  =  m[0]*m[10]*m[15] - m[0]*m[11]*m[14] - m[8]*m[2]*m[15] + m[8]*m[3]*m[14] + m[12]*m[2]*m[11] - m[12]*m[3]*m[10];
    inv[9]  = -m[0]*m[9]*m[15]  + m[0]*m[11]*m[13] + m[8]*m[1]*m[15] - m[8]*m[3]*m[13] - m[12]*m[1]*m[11] + m[12]*m[3]*m[9];
    inv[13] =  m[0]*m[9]*m[14]  - m[0]*m[10]*m[13] - m[8]*m[1]*m[14] + m[8]*m[2]*m[13] + m[12]*m[1]*m[10] - m[12]*m[2]*m[9];
    inv[2]  =  m[1]*m[6]*m[15]  - m[1]*m[7]*m[14]  - m[5]*m[2]*m[15] + m[5]*m[3]*m[14] + m[13]*m[2]*m[7]  - m[13]*m[3]*m[6];
    inv[6]  = -m[0]*m[6]*m[15]  + m[0]*m[7]*m[14]  + m[4]*m[2]*m[15] - m[4]*m[3]*m[14] - m[12]*m[2]*m[7]  + m[12]*m[3]*m[6];
    inv[10] =  m[0]*m[5]*m[15]  - m[0]*m[7]*m[13]  - m[4]*m[1]*m[15] + m[4]*m[3]*m[13] + m[12]*m[1]*m[7]  - m[12]*m[3]*m[5];
    inv[14] = -m[0]*m[5]*m[14]  + m[0]*m[6]*m[13]  + m[4]*m[1]*m[14] - m[4]*m[2]*m[13] - m[12]*m[1]*m[6]  + m[12]*m[2]*m[5];
    inv[3]  = -m[1]*m[6]*m[11]  + m[1]*m[7]*m[10]  + m[5]*m[2]*m[11] - m[5]*m[3]*m[10] - m[9]*m[2]*m[7]   + m[9]*m[3]*m[6];
    inv[7]  =  m[0]*m[6]*m[11]  - m[0]*m[7]*m[10]  - m[4]*m[2]*m[11] + m[4]*m[3]*m[10] + m[8]*m[2]*m[7]   - m[8]*m[3]*m[6];
    inv[11] = -m[0]*m[5]*m[11]  + m[0]*m[7]*m[9]   + m[4]*m[1]*m[11] - m[4]*m[3]*m[9]  - m[8]*m[1]*m[7]   + m[8]*m[3]*m[5];
    inv[15] =  m[0]*m[5]*m[10]  - m[0]*m[6]*m[9]   - m[4]*m[1]*m[10] + m[4]*m[2]*m[9]  + m[8]*m[1]*m[6]   - m[8]*m[2]*m[5];

    float det = m[0]*inv[0] + m[1]*inv[4] + m[2]*inv[8] + m[3]*inv[12];
    float rd = __fdiv_rn(1.0f, det);
#pragma unroll
    for (int i = 0; i < 12; i++) g_invpose[v * 12 + i] = inv[i] * rd;
}

// ---------------------------------------------------------------------------
// Kernel 2: transpose feats (V,C,H,W) -> (V,H*W,CP) with zero pad at c=47.
// ---------------------------------------------------------------------------
__global__ void transpose_kernel(const float* __restrict__ feats) {
    int idx = blockIdx.x * blockDim.x + threadIdx.x;   // over BV*HW
    if (idx >= BV * HW) return;
    int v = idx / HW, pp = idx - v * HW;
    const float* src = feats + (size_t)v * CC * HW + pp;
    float4* dst = reinterpret_cast<float4*>(g_feats_t) + (size_t)idx * 12;
#pragma unroll
    for (int i = 0; i < 12; i++) {
        float4 val;
        val.x = src[(4 * i + 0) * HW];
        val.y = src[(4 * i + 1) * HW];
        val.z = src[(4 * i + 2) * HW];
        val.w = (4 * i + 3 < CC) ? src[(4 * i + 3) * HW] : 0.0f;
        dst[i] = val;
    }
}

// cam row dot: rows of [I|-t] make every product exact -> single rounding,
// order-independent.
__device__ __forceinline__ float dot4_exact(const float* M, float a, float b, float c) {
    float p0 = __fmul_rn(M[0], a);
    float p1 = __fmul_rn(M[1], b);
    float p2 = __fmul_rn(M[2], c);
    return __fadd_rn(__fadd_rn(__fadd_rn(p0, p1), p2), M[3]);
}

// ---------------------------------------------------------------------------
// Kernel 3: fused projection + sampling + accumulation.
//
// NUMERICS MODEL (this round): XLA rewrites  A / broadcast(B)  into
// A * broadcast(1/B), so the reference computes
//     r = rn(1 / z_safe);   u = rn(uw * r);   v = rn(vw * r)
// (NOT rn(uw/z)).  Numerator in non-contracted form A:
//     uw = rn( rn(f*c0) + rn(cx*c2) )      (middle zero product exact).
// ---------------------------------------------------------------------------
__global__ void __launch_bounds__(THREADS) fuse_kernel(
    const float* __restrict__ pred_depth,
    const float* __restrict__ Kc_all,
    const float* __restrict__ Kd_all,
    const float* __restrict__ coords,
    float* __restrict__ out)
{
    __shared__ float4 s_pv[PB * BV];       // {w, wx, wy, bits}
    __shared__ __align__(16) float s_dens[PB * CP];
    __shared__ float s_coords[PB * 3];
    __shared__ float s_cam[BV * 30];       // invpose(12) + Kc(9) + Kd(9)

    int tid = threadIdx.x;
    int base = blockIdx.x * PB;

    if (tid < BV * 30) {
        int v = tid / 30, j = tid - v * 30;
        float val;
        if (j < 12)      val = g_invpose[v * 12 + j];
        else if (j < 21) val = Kc_all[v * 9 + (j - 12)];
        else             val = Kd_all[v * 9 + (j - 21)];
        s_cam[tid] = val;
    }
    for (int i = tid; i < PB * 3; i += THREADS) {
        int gi = base * 3 + i;
        s_coords[i] = (gi < NPTS * 3) ? coords[gi] : 0.0f;
    }
    __syncthreads();

    // ---------------- Phase A: thread-per-(point,view) ----------------
    for (int item = tid; item < PB * BV; item += THREADS) {
        int p = item >> 3, v = item & 7;
        int n = base + p;
        float4 pv = make_float4(0.f, 0.f, 0.f, __int_as_float(0));
        if (n < NPTS) {
            float x = s_coords[p * 3 + 0];
            float y = s_coords[p * 3 + 1];
            float zc = s_coords[p * 3 + 2];
            const float* M = s_cam + v * 30;
            float c0 = dot4_exact(M + 0, x, y, zc);
            float c1 = dot4_exact(M + 4, x, y, zc);
            float c2 = dot4_exact(M + 8, x, y, zc);

            // Numerators, form A (separate product roundings, left-assoc sum).
            const float* Kc = M + 12;
            float uwc = __fadd_rn(__fmul_rn(Kc[0], c0), __fmul_rn(Kc[2], c2));
            float vwc = __fadd_rn(__fmul_rn(Kc[4], c1), __fmul_rn(Kc[5], c2));
            const float* Kd = M + 21;
            float uwd = __fadd_rn(__fmul_rn(Kd[0], c0), __fmul_rn(Kd[2], c2));
            float vwd = __fadd_rn(__fmul_rn(Kd[4], c1), __fmul_rn(Kd[5], c2));
            float wwc = c2, wwd = c2;

            // XLA broadcast-division rewrite: multiply by rounded reciprocal.
            float zsc = (fabsf(wwc) > 1e-6f) ? wwc : 1e-6f;
            float zsd = (fabsf(wwd) > 1e-6f) ? wwd : 1e-6f;
            float rcc = __frcp_rn(zsc);
            float rcd = __frcp_rn(zsd);
            float uc = __fmul_rn(uwc, rcc), vc = __fmul_rn(vwc, rcc);
            float ud = __fmul_rn(uwd, rcd), vd = __fmul_rn(vwd, rcd);

            bool validc = (uc >= 0.f) && (uc <= (float)(FWw - 1)) &&
                          (vc >= 0.f) && (vc <= (float)(FHh - 1));
            bool validd = (ud >= 0.f) && (ud <= (float)(DWw - 1)) &&
                          (vd >= 0.f) && (vd <= (float)(DHh - 1));

            // nearest depth sample (rintf == round-half-even == jnp.round)
            int xi = (int)fminf(fmaxf(rintf(ud), 0.f), (float)(DWw - 1));
            int yi = (int)fminf(fmaxf(rintf(vd), 0.f), (float)(DHh - 1));
            float dep = pred_depth[(v * DHh + yi) * DWw + xi];

            bool valid = validc && validd && (c2 > 0.f) && (dep > 0.f);
            float dist = fabsf(__fadd_rn(c2, -dep));
            float t16 = __fmul_rn(dist, 16.0f);
            float w = __fmul_rn(expf(-__fmul_rn(t16, t16)), (valid ? 1.0f : 0.0f));

            // bilinear setup (clipped coords)
            float u  = fminf(fmaxf(uc, 0.f), (float)(FWw - 1));
            float vv = fminf(fmaxf(vc, 0.f), (float)(FHh - 1));
            float x0f = floorf(u), y0f = floorf(vv);
            int x0 = (int)x0f, y0 = (int)y0f;
            int dx = (x0 < FWw - 1) ? 1 : 0;
            int dy = (y0 < FHh - 1) ? 1 : 0;
            int bp = v * HW + y0 * FWw + x0;
            int bits = (bp << 3) | (dx << 2) | (dy << 1) | (valid ? 1 : 0);
            pv = make_float4(w, __fadd_rn(u, -x0f), __fadd_rn(vv, -y0f), __int_as_float(bits));
        }
        s_pv[item] = pv;   // item == p*8 + v
    }
    __syncthreads();

    // ---------------- Phase B: warp-per-point gather ----------------
    int warp = tid >> 5, lane = tid & 31;
    for (int p = warp; p < PB; p += (THREADS / 32)) {
        int n = base + p;
        if (n >= NPTS) break;
        float4 acc = make_float4(0.f, 0.f, 0.f, 0.f);
#pragma unroll
        for (int v = 0; v < BV; v++) {
            float4 pv = s_pv[p * 8 + v];   // broadcast
            if (pv.x == 0.f) continue;     // warp-uniform skip (w==0 adds exact 0)
            int bits = __float_as_int(pv.w);
            int bp  = bits >> 3;
            int o01 = ((bits >> 2) & 1) * 12;
            int o10 = ((bits >> 1) & 1) * (FWw * 12);
            const float4* fptr = reinterpret_cast<const float4*>(g_feats_t) + (size_t)bp * 12;
            if (lane < 12) {
                float4 a = fptr[lane];
                float4 b = fptr[o01 + lane];
                float4 c = fptr[o10 + lane];
                float4 d = fptr[o01 + o10 + lane];
                float wx = pv.y, wy = pv.z;
                float owx = __fadd_rn(1.f, -wx);
                float owy = __fadd_rn(1.f, -wy);
                float w = pv.x;
#define BILIN(FLD)                                                          \
                {                                                           \
                    float t0 = __fmul_rn(__fmul_rn(a.FLD, owy), owx);       \
                    float t1 = __fmul_rn(__fmul_rn(b.FLD, owy), wx);        \
                    float t2 = __fmul_rn(__fmul_rn(c.FLD, wy),  owx);       \
                    float t3 = __fmul_rn(__fmul_rn(d.FLD, wy),  wx);        \
                    float s  = __fadd_rn(__fadd_rn(__fadd_rn(t0, t1), t2), t3); \
                    acc.FLD  = __fadd_rn(acc.FLD, __fmul_rn(s, w));         \
                }
                BILIN(x) BILIN(y) BILIN(z) BILIN(w)
#undef BILIN
            }
        }
        if (lane < 12)
            reinterpret_cast<float4*>(s_dens)[p * 12 + lane] = acc;
    }
    __syncthreads();

    // ---------------- Phase C: coalesced output ----------------
    float* dens_out = out;
    float* ws_out   = out + (size_t)CC * NPTS;
    float* cnt_out  = out + (size_t)CC * NPTS + NPTS;

    if (tid < PB) {
        int p = tid, n = base + p;
        if (n < NPTS) {
            float ws = 0.f, ct = 0.f;
#pragma unroll
            for (int v = 0; v < BV; v++) {
                float4 pv = s_pv[p * 8 + v];
                ws = __fadd_rn(ws, pv.x);
                ct = __fadd_rn(ct, (float)(__float_as_int(pv.w) & 1));
            }
            ws_out[n]  = ws;
            cnt_out[n] = ct;
        }
    }
    for (int i = tid; i < CC * PB; i += THREADS) {
        int c = i >> 7;          // PB == 128
        int p = i & (PB - 1);
        int n = base + p;
        if (n < NPTS) dens_out[(size_t)c * NPTS + n] = s_dens[p * CP + c];
    }
}

// ---------------------------------------------------------------------------
extern "C" void kernel_launch(void* const* d_in, const int* in_sizes, int n_in,
                              void* d_out, int out_size) {
    const float* img_feats  = (const float*)d_in[0];
    const float* pred_depth = (const float*)d_in[1];
    const float* poses      = (const float*)d_in[2];
    const float* Kc         = (const float*)d_in[3];
    const float* Kd         = (const float*)d_in[4];
    const float* coords     = (const float*)d_in[5];
    float* out = (float*)d_out;

    prep_poses_kernel<<<1, 32>>>(poses);
    transpose_kernel<<<(BV * HW + 255) / 256, 256>>>(img_feats);
    int blocks = (NPTS + PB - 1) / PB;
    fuse_kernel<<<blocks, THREADS>>>(pred_depth, Kc, Kd, coords, out);
}

// round 16
// speedup vs baseline: 1.1881x; 1.1881x over previous
#include <cuda_runtime.h>

// Problem constants
#define BV   8        // views
#define CC   47       // channels
#define CP   48       // padded channels (12 float4)
#define FHh  60
#define FWw  80
#define HW   (FHh*FWw)        // 4800
#define DHh  240
#define DWw  320
#define NPTS 150000
#define PB   128      // points per block
#define THREADS 512
#define NWARPS (THREADS/32)

// Transposed features: (V, H, W, CP) for contiguous per-pixel channel runs.
__device__ __align__(16) float g_feats_t[BV * HW * CP];   // ~7.4 MB
__device__ float g_invpose[BV * 12];                       // rows 0..2 of pose^-1

// ---------------------------------------------------------------------------
// Kernel 1: transpose feats (V,C,H,W) -> (V,H*W,CP) with zero pad at c=47,
// AND (one warp of the last block) invert the 8 poses — merged to save a
// kernel launch. Pose inverse: general 4x4 adjugate; for these poses ([I|t])
// the result is exactly [I|-t] (det=1) matching the reference's f32 LU inverse.
// ---------------------------------------------------------------------------
__global__ void prep_kernel(const float* __restrict__ feats,
                            const float* __restrict__ poses) {
    if (blockIdx.x == gridDim.x - 1 && threadIdx.x < BV) {
        int v = threadIdx.x;
        float m[16];
#pragma unroll
        for (int i = 0; i < 16; i++) m[i] = poses[v * 16 + i];
        float inv[16];
        inv[0]  =  m[5]*m[10]*m[15] - m[5]*m[11]*m[14] - m[9]*m[6]*m[15] + m[9]*m[7]*m[14] + m[13]*m[6]*m[11] - m[13]*m[7]*m[10];
        inv[4]  = -m[4]*m[10]*m[15] + m[4]*m[11]*m[14] + m[8]*m[6]*m[15] - m[8]*m[7]*m[14] - m[12]*m[6]*m[11] + m[12]*m[7]*m[10];
        inv[8]  =  m[4]*m[9]*m[15]  - m[4]*m[11]*m[13] - m[8]*m[5]*m[15] + m[8]*m[7]*m[13] + m[12]*m[5]*m[11] - m[12]*m[7]*m[9];
        inv[12] = -m[4]*m[9]*m[14]  + m[4]*m[10]*m[13] + m[8]*m[5]*m[14] - m[8]*m[6]*m[13] - m[12]*m[5]*m[10] + m[12]*m[6]*m[9];
        inv[1]  = -m[1]*m[10]*m[15] + m[1]*m[11]*m[14] + m[9]*m[2]*m[15] - m[9]*m[3]*m[14] - m[13]*m[2]*m[11] + m[13]*m[3]*m[10];
        inv[5]  =  m[0]*m[10]*m[15] - m[0]*m[11]*m[14] - m[8]*m[2]*m[15] + m[8]*m[3]*m[14] + m[12]*m[2]*m[11] - m[12]*m[3]*m[10];
        inv[9]  = -m[0]*m[9]*m[15]  + m[0]*m[11]*m[13] + m[8]*m[1]*m[15] - m[8]*m[3]*m[13] - m[12]*m[1]*m[11] + m[12]*m[3]*m[9];
        inv[13] =  m[0]*m[9]*m[14]  - m[0]*m[10]*m[13] - m[8]*m[1]*m[14] + m[8]*m[2]*m[13] + m[12]*m[1]*m[10] - m[12]*m[2]*m[9];
        inv[2]  =  m[1]*m[6]*m[15]  - m[1]*m[7]*m[14]  - m[5]*m[2]*m[15] + m[5]*m[3]*m[14] + m[13]*m[2]*m[7]  - m[13]*m[3]*m[6];
        inv[6]  = -m[0]*m[6]*m[15]  + m[0]*m[7]*m[14]  + m[4]*m[2]*m[15] - m[4]*m[3]*m[14] - m[12]*m[2]*m[7]  + m[12]*m[3]*m[6];
        inv[10] =  m[0]*m[5]*m[15]  - m[0]*m[7]*m[13]  - m[4]*m[1]*m[15] + m[4]*m[3]*m[13] + m[12]*m[1]*m[7]  - m[12]*m[3]*m[5];
        inv[14] = -m[0]*m[5]*m[14]  + m[0]*m[6]*m[13]  + m[4]*m[1]*m[14] - m[4]*m[2]*m[13] - m[12]*m[1]*m[6]  + m[12]*m[2]*m[5];
        inv[3]  = -m[1]*m[6]*m[11]  + m[1]*m[7]*m[10]  + m[5]*m[2]*m[11] - m[5]*m[3]*m[10] - m[9]*m[2]*m[7]   + m[9]*m[3]*m[6];
        inv[7]  =  m[0]*m[6]*m[11]  - m[0]*m[7]*m[10]  - m[4]*m[2]*m[11] + m[4]*m[3]*m[10] + m[8]*m[2]*m[7]   - m[8]*m[3]*m[6];
        inv[11] = -m[0]*m[5]*m[11]  + m[0]*m[7]*m[9]   + m[4]*m[1]*m[11] - m[4]*m[3]*m[9]  - m[8]*m[1]*m[7]   + m[8]*m[3]*m[5];
        inv[15] =  m[0]*m[5]*m[10]  - m[0]*m[6]*m[9]   - m[4]*m[1]*m[10] + m[4]*m[2]*m[9]  + m[8]*m[1]*m[6]   - m[8]*m[2]*m[5];
        float det = m[0]*inv[0] + m[1]*inv[4] + m[2]*inv[8] + m[3]*inv[12];
        float rd = __fdiv_rn(1.0f, det);
#pragma unroll
        for (int i = 0; i < 12; i++) g_invpose[v * 12 + i] = inv[i] * rd;
    }

    int idx = blockIdx.x * blockDim.x + threadIdx.x;   // over BV*HW
    if (idx >= BV * HW) return;
    int v = idx / HW, pp = idx - v * HW;
    const float* src = feats + (size_t)v * CC * HW + pp;
    float4* dst = reinterpret_cast<float4*>(g_feats_t) + (size_t)idx * 12;
#pragma unroll
    for (int i = 0; i < 12; i++) {
        float4 val;
        val.x = src[(4 * i + 0) * HW];
        val.y = src[(4 * i + 1) * HW];
        val.z = src[(4 * i + 2) * HW];
        val.w = (4 * i + 3 < CC) ? src[(4 * i + 3) * HW] : 0.0f;
        dst[i] = val;
    }
}

// cam row dot: rows of [I|-t] make every product exact -> single rounding,
// order-independent.
__device__ __forceinline__ float dot4_exact(const float* M, float a, float b, float c) {
    float p0 = __fmul_rn(M[0], a);
    float p1 = __fmul_rn(M[1], b);
    float p2 = __fmul_rn(M[2], c);
    return __fadd_rn(__fadd_rn(__fadd_rn(p0, p1), p2), M[3]);
}

// ---------------------------------------------------------------------------
// Kernel 2: fused projection + sampling + accumulation.
//
// NUMERICS (verified passing, rel_err 5e-8 — DO NOT CHANGE):
//   - numerators: form A   uw = rn( rn(f*c0) + rn(cx*c2) )
//   - division:   XLA broadcast rewrite  r = rn(1/z_safe); u = rn(uw*r)
// ---------------------------------------------------------------------------
__global__ void __launch_bounds__(THREADS) fuse_kernel(
    const float* __restrict__ pred_depth,
    const float* __restrict__ Kc_all,
    const float* __restrict__ Kd_all,
    const float* __restrict__ coords,
    float* __restrict__ out)
{
    __shared__ float4 s_pv[PB * BV];       // {w, wx, wy, bits}
    __shared__ __align__(16) float s_dens[PB * CP];
    __shared__ float s_coords[PB * 3];
    __shared__ float s_cam[BV * 30];       // invpose(12) + Kc(9) + Kd(9)

    int tid = threadIdx.x;
    int base = blockIdx.x * PB;

    if (tid < BV * 30) {
        int v = tid / 30, j = tid - v * 30;
        float val;
        if (j < 12)      val = g_invpose[v * 12 + j];
        else if (j < 21) val = Kc_all[v * 9 + (j - 12)];
        else             val = Kd_all[v * 9 + (j - 21)];
        s_cam[tid] = val;
    }
    if (tid < PB * 3) {
        int gi = base * 3 + tid;
        s_coords[tid] = (gi < NPTS * 3) ? coords[gi] : 0.0f;
    }
    __syncthreads();

    // ---------------- Phase A: thread-per-(point,view) ----------------
    for (int item = tid; item < PB * BV; item += THREADS) {
        int p = item >> 3, v = item & 7;
        int n = base + p;
        float4 pv = make_float4(0.f, 0.f, 0.f, __int_as_float(0));
        if (n < NPTS) {
            float x = s_coords[p * 3 + 0];
            float y = s_coords[p * 3 + 1];
            float zc = s_coords[p * 3 + 2];
            const float* M = s_cam + v * 30;
            float c0 = dot4_exact(M + 0, x, y, zc);
            float c1 = dot4_exact(M + 4, x, y, zc);
            float c2 = dot4_exact(M + 8, x, y, zc);

            // Numerators, form A (separate product roundings, left-assoc sum).
            const float* Kc = M + 12;
            float uwc = __fadd_rn(__fmul_rn(Kc[0], c0), __fmul_rn(Kc[2], c2));
            float vwc = __fadd_rn(__fmul_rn(Kc[4], c1), __fmul_rn(Kc[5], c2));
            const float* Kd = M + 21;
            float uwd = __fadd_rn(__fmul_rn(Kd[0], c0), __fmul_rn(Kd[2], c2));
            float vwd = __fadd_rn(__fmul_rn(Kd[4], c1), __fmul_rn(Kd[5], c2));

            // XLA broadcast-division rewrite: multiply by rounded reciprocal.
            float zsc = (fabsf(c2) > 1e-6f) ? c2 : 1e-6f;
            float rcc = __frcp_rn(zsc);
            float uc = __fmul_rn(uwc, rcc), vc = __fmul_rn(vwc, rcc);
            float ud = __fmul_rn(uwd, rcc), vd = __fmul_rn(vwd, rcc);

            bool validc = (uc >= 0.f) && (uc <= (float)(FWw - 1)) &&
                          (vc >= 0.f) && (vc <= (float)(FHh - 1));
            bool validd = (ud >= 0.f) && (ud <= (float)(DWw - 1)) &&
                          (vd >= 0.f) && (vd <= (float)(DHh - 1));

            // nearest depth sample (rintf == round-half-even == jnp.round)
            int xi = (int)fminf(fmaxf(rintf(ud), 0.f), (float)(DWw - 1));
            int yi = (int)fminf(fmaxf(rintf(vd), 0.f), (float)(DHh - 1));
            float dep = pred_depth[(v * DHh + yi) * DWw + xi];

            bool valid = validc && validd && (c2 > 0.f) && (dep > 0.f);
            float dist = fabsf(__fadd_rn(c2, -dep));
            float t16 = __fmul_rn(dist, 16.0f);
            float w = __fmul_rn(expf(-__fmul_rn(t16, t16)), (valid ? 1.0f : 0.0f));

            // bilinear setup (clipped coords)
            float u  = fminf(fmaxf(uc, 0.f), (float)(FWw - 1));
            float vv = fminf(fmaxf(vc, 0.f), (float)(FHh - 1));
            float x0f = floorf(u), y0f = floorf(vv);
            int x0 = (int)x0f, y0 = (int)y0f;
            int dx = (x0 < FWw - 1) ? 1 : 0;
            int dy = (y0 < FHh - 1) ? 1 : 0;
            int bp = v * HW + y0 * FWw + x0;
            int bits = (bp << 3) | (dx << 2) | (dy << 1) | (valid ? 1 : 0);
            pv = make_float4(w, __fadd_rn(u, -x0f), __fadd_rn(vv, -y0f), __int_as_float(bits));
        }
        s_pv[item] = pv;   // item == p*8 + v
    }
    __syncthreads();

    // ---------------- Phase B: TWO points per warp ----------------
    // lanes 0-11 handle even point, lanes 16-27 handle odd point.
    {
        int warp = tid >> 5, lane = tid & 31;
        int sub = lane >> 4;          // 0 or 1
        int l   = lane & 15;          // 0..15, use l < 12
        bool ch_act = (l < 12);
        for (int pp = warp; pp < PB / 2; pp += NWARPS) {
            int p = pp * 2 + sub;
            float4 acc = make_float4(0.f, 0.f, 0.f, 0.f);
#pragma unroll
            for (int v = 0; v < BV; v++) {
                float4 pv = s_pv[p * 8 + v];   // half-warp broadcast
                if (pv.x != 0.f && ch_act) {   // inactive => predicated off
                    int bits = __float_as_int(pv.w);
                    int bp  = bits >> 3;
                    int o01 = ((bits >> 2) & 1) * 12;
                    int o10 = ((bits >> 1) & 1) * (FWw * 12);
                    const float4* fptr = reinterpret_cast<const float4*>(g_feats_t) + (size_t)bp * 12;
                    float4 a = fptr[l];
                    float4 b = fptr[o01 + l];
                    float4 c = fptr[o10 + l];
                    float4 d = fptr[o01 + o10 + l];
                    float wx = pv.y, wy = pv.z;
                    float owx = __fadd_rn(1.f, -wx);
                    float owy = __fadd_rn(1.f, -wy);
                    float w = pv.x;
#define BILIN(FLD)                                                          \
                    {                                                       \
                        float t0 = __fmul_rn(__fmul_rn(a.FLD, owy), owx);   \
                        float t1 = __fmul_rn(__fmul_rn(b.FLD, owy), wx);    \
                        float t2 = __fmul_rn(__fmul_rn(c.FLD, wy),  owx);   \
                        float t3 = __fmul_rn(__fmul_rn(d.FLD, wy),  wx);    \
                        float s  = __fadd_rn(__fadd_rn(__fadd_rn(t0, t1), t2), t3); \
                        acc.FLD  = __fadd_rn(acc.FLD, __fmul_rn(s, w));     \
                    }
                    BILIN(x) BILIN(y) BILIN(z) BILIN(w)
#undef BILIN
                }
            }
            if (ch_act)
                reinterpret_cast<float4*>(s_dens)[p * 12 + l] = acc;
        }
    }
    __syncthreads();

    // ---------------- Phase C: coalesced output ----------------
    float* dens_out = out;
    float* ws_out   = out + (size_t)CC * NPTS;
    float* cnt_out  = out + (size_t)CC * NPTS + NPTS;

    if (tid < PB) {
        int p = tid, n = base + p;
        if (n < NPTS) {
            float ws = 0.f, ct = 0.f;
#pragma unroll
            for (int v = 0; v < BV; v++) {
                float4 pv = s_pv[p * 8 + v];
                ws = __fadd_rn(ws, pv.x);
                ct = __fadd_rn(ct, (float)(__float_as_int(pv.w) & 1));
            }
            ws_out[n]  = ws;
            cnt_out[n] = ct;
        }
    }
    for (int i = tid; i < CC * PB; i += THREADS) {
        int c = i >> 7;          // PB == 128
        int p = i & (PB - 1);
        int n = base + p;
        if (n < NPTS) dens_out[(size_t)c * NPTS + n] = s_dens[p * CP + c];
    }
}

// ---------------------------------------------------------------------------
extern "C" void kernel_launch(void* const* d_in, const int* in_sizes, int n_in,
                              void* d_out, int out_size) {
    const float* img_feats  = (const float*)d_in[0];
    const float* pred_depth = (const float*)d_in[1];
    const float* poses      = (const float*)d_in[2];
    const float* Kc         = (const float*)d_in[3];
    const float* Kd         = (const float*)d_in[4];
    const float* coords     = (const float*)d_in[5];
    float* out = (float*)d_out;

    prep_kernel<<<(BV * HW + 255) / 256, 256>>>(img_feats, poses);
    int blocks = (NPTS + PB - 1) / PB;
    fuse_kernel<<<blocks, THREADS>>>(pred_depth, Kc, Kd, coords, out);
}

// round 17
// speedup vs baseline: 1.3237x; 1.1141x over previous
#include <cuda_runtime.h>

// Problem constants
#define BV   8        // views
#define CC   47       // channels
#define CP   48       // padded channels (12 float4)
#define FHh  60
#define FWw  80
#define HW   (FHh*FWw)        // 4800
#define DHh  240
#define DWw  320
#define NPTS 150000
#define PB   128      // points per block
#define THREADS 512
#define NWARPS (THREADS/32)

// Transposed features: (V, H, W, CP) for contiguous per-pixel channel runs.
__device__ __align__(16) float g_feats_t[BV * HW * CP];   // ~7.4 MB
__device__ float g_invpose[BV * 12];                       // rows 0..2 of pose^-1

// ---------------------------------------------------------------------------
// Kernel 1: transpose feats (V,C,H,W) -> (V,H*W,CP) with zero pad at c=47,
// AND (one warp of the last block) invert the 8 poses — merged to save a
// kernel launch. Pose inverse: general 4x4 adjugate; for these poses ([I|t])
// the result is exactly [I|-t] (det=1) matching the reference's f32 LU inverse.
// ---------------------------------------------------------------------------
__global__ void prep_kernel(const float* __restrict__ feats,
                            const float* __restrict__ poses) {
    if (blockIdx.x == gridDim.x - 1 && threadIdx.x < BV) {
        int v = threadIdx.x;
        float m[16];
#pragma unroll
        for (int i = 0; i < 16; i++) m[i] = poses[v * 16 + i];
        float inv[16];
        inv[0]  =  m[5]*m[10]*m[15] - m[5]*m[11]*m[14] - m[9]*m[6]*m[15] + m[9]*m[7]*m[14] + m[13]*m[6]*m[11] - m[13]*m[7]*m[10];
        inv[4]  = -m[4]*m[10]*m[15] + m[4]*m[11]*m[14] + m[8]*m[6]*m[15] - m[8]*m[7]*m[14] - m[12]*m[6]*m[11] + m[12]*m[7]*m[10];
        inv[8]  =  m[4]*m[9]*m[15]  - m[4]*m[11]*m[13] - m[8]*m[5]*m[15] + m[8]*m[7]*m[13] + m[12]*m[5]*m[11] - m[12]*m[7]*m[9];
        inv[12] = -m[4]*m[9]*m[14]  + m[4]*m[10]*m[13] + m[8]*m[5]*m[14] - m[8]*m[6]*m[13] - m[12]*m[5]*m[10] + m[12]*m[6]*m[9];
        inv[1]  = -m[1]*m[10]*m[15] + m[1]*m[11]*m[14] + m[9]*m[2]*m[15] - m[9]*m[3]*m[14] - m[13]*m[2]*m[11] + m[13]*m[3]*m[10];
        inv[5]  =  m[0]*m[10]*m[15] - m[0]*m[11]*m[14] - m[8]*m[2]*m[15] + m[8]*m[3]*m[14] + m[12]*m[2]*m[11] - m[12]*m[3]*m[10];
        inv[9]  = -m[0]*m[9]*m[15]  + m[0]*m[11]*m[13] + m[8]*m[1]*m[15] - m[8]*m[3]*m[13] - m[12]*m[1]*m[11] + m[12]*m[3]*m[9];
        inv[13] =  m[0]*m[9]*m[14]  - m[0]*m[10]*m[13] - m[8]*m[1]*m[14] + m[8]*m[2]*m[13] + m[12]*m[1]*m[10] - m[12]*m[2]*m[9];
        inv[2]  =  m[1]*m[6]*m[15]  - m[1]*m[7]*m[14]  - m[5]*m[2]*m[15] + m[5]*m[3]*m[14] + m[13]*m[2]*m[7]  - m[13]*m[3]*m[6];
        inv[6]  = -m[0]*m[6]*m[15]  + m[0]*m[7]*m[14]  + m[4]*m[2]*m[15] - m[4]*m[3]*m[14] - m[12]*m[2]*m[7]  + m[12]*m[3]*m[6];
        inv[10] =  m[0]*m[5]*m[15]  - m[0]*m[7]*m[13]  - m[4]*m[1]*m[15] + m[4]*m[3]*m[13] + m[12]*m[1]*m[7]  - m[12]*m[3]*m[5];
        inv[14] = -m[0]*m[5]*m[14]  + m[0]*m[6]*m[13]  + m[4]*m[1]*m[14] - m[4]*m[2]*m[13] - m[12]*m[1]*m[6]  + m[12]*m[2]*m[5];
        inv[3]  = -m[1]*m[6]*m[11]  + m[1]*m[7]*m[10]  + m[5]*m[2]*m[11] - m[5]*m[3]*m[10] - m[9]*m[2]*m[7]   + m[9]*m[3]*m[6];
        inv[7]  =  m[0]*m[6]*m[11]  - m[0]*m[7]*m[10]  - m[4]*m[2]*m[11] + m[4]*m[3]*m[10] + m[8]*m[2]*m[7]   - m[8]*m[3]*m[6];
        inv[11] = -m[0]*m[5]*m[11]  + m[0]*m[7]*m[9]   + m[4]*m[1]*m[11] - m[4]*m[3]*m[9]  - m[8]*m[1]*m[7]   + m[8]*m[3]*m[5];
        inv[15] =  m[0]*m[5]*m[10]  - m[0]*m[6]*m[9]   - m[4]*m[1]*m[10] + m[4]*m[2]*m[9]  + m[8]*m[1]*m[6]   - m[8]*m[2]*m[5];
        float det = m[0]*inv[0] + m[1]*inv[4] + m[2]*inv[8] + m[3]*inv[12];
        float rd = __fdiv_rn(1.0f, det);
#pragma unroll
        for (int i = 0; i < 12; i++) g_invpose[v * 12 + i] = inv[i] * rd;
    }

    int idx = blockIdx.x * blockDim.x + threadIdx.x;   // over BV*HW
    if (idx >= BV * HW) return;
    int v = idx / HW, pp = idx - v * HW;
    const float* src = feats + (size_t)v * CC * HW + pp;
    float4* dst = reinterpret_cast<float4*>(g_feats_t) + (size_t)idx * 12;
#pragma unroll
    for (int i = 0; i < 12; i++) {
        float4 val;
        val.x = src[(4 * i + 0) * HW];
        val.y = src[(4 * i + 1) * HW];
        val.z = src[(4 * i + 2) * HW];
        val.w = (4 * i + 3 < CC) ? src[(4 * i + 3) * HW] : 0.0f;
        dst[i] = val;
    }
}

// cam row dot: rows of [I|-t] make every product exact -> single rounding,
// order-independent.
__device__ __forceinline__ float dot4_exact(const float* M, float a, float b, float c) {
    float p0 = __fmul_rn(M[0], a);
    float p1 = __fmul_rn(M[1], b);
    float p2 = __fmul_rn(M[2], c);
    return __fadd_rn(__fadd_rn(__fadd_rn(p0, p1), p2), M[3]);
}

// ---------------------------------------------------------------------------
// Kernel 2: fused projection + sampling + accumulation.
//
// NUMERICS (verified passing, rel_err 5e-8 — DO NOT CHANGE):
//   - numerators: form A   uw = rn( rn(f*c0) + rn(cx*c2) )
//   - division:   XLA broadcast rewrite  r = rn(1/z_safe); u = rn(uw*r)
//   - accumulation ascending v over w!=0 views (zero-weight adds exact 0)
// ---------------------------------------------------------------------------
__global__ void __launch_bounds__(THREADS, 4) fuse_kernel(
    const float* __restrict__ pred_depth,
    const float* __restrict__ Kc_all,
    const float* __restrict__ Kd_all,
    const float* __restrict__ coords,
    float* __restrict__ out)
{
    __shared__ float4 s_pv[PB * BV];       // {w, wx, wy, bits}
    __shared__ __align__(16) float s_dens[PB * CP];
    __shared__ float s_coords[PB * 3];
    __shared__ float s_cam[BV * 30];       // invpose(12) + Kc(9) + Kd(9)
    __shared__ int   s_mask[PB];           // active-view bitmask per point

    int tid = threadIdx.x;
    int base = blockIdx.x * PB;

    if (tid < BV * 30) {
        int v = tid / 30, j = tid - v * 30;
        float val;
        if (j < 12)      val = g_invpose[v * 12 + j];
        else if (j < 21) val = Kc_all[v * 9 + (j - 12)];
        else             val = Kd_all[v * 9 + (j - 21)];
        s_cam[tid] = val;
    }
    if (tid < PB * 3) {
        int gi = base * 3 + tid;
        s_coords[tid] = (gi < NPTS * 3) ? coords[gi] : 0.0f;
    }
    if (tid >= THREADS - PB) s_mask[tid - (THREADS - PB)] = 0;
    __syncthreads();

    // ---------------- Phase A: thread-per-(point,view) ----------------
    for (int item = tid; item < PB * BV; item += THREADS) {
        int p = item >> 3, v = item & 7;
        int n = base + p;
        float4 pv = make_float4(0.f, 0.f, 0.f, __int_as_float(0));
        if (n < NPTS) {
            float x = s_coords[p * 3 + 0];
            float y = s_coords[p * 3 + 1];
            float zc = s_coords[p * 3 + 2];
            const float* M = s_cam + v * 30;
            float c0 = dot4_exact(M + 0, x, y, zc);
            float c1 = dot4_exact(M + 4, x, y, zc);
            float c2 = dot4_exact(M + 8, x, y, zc);

            // Numerators, form A (separate product roundings, left-assoc sum).
            const float* Kc = M + 12;
            float uwc = __fadd_rn(__fmul_rn(Kc[0], c0), __fmul_rn(Kc[2], c2));
            float vwc = __fadd_rn(__fmul_rn(Kc[4], c1), __fmul_rn(Kc[5], c2));
            const float* Kd = M + 21;
            float uwd = __fadd_rn(__fmul_rn(Kd[0], c0), __fmul_rn(Kd[2], c2));
            float vwd = __fadd_rn(__fmul_rn(Kd[4], c1), __fmul_rn(Kd[5], c2));

            // XLA broadcast-division rewrite: multiply by rounded reciprocal.
            float zsc = (fabsf(c2) > 1e-6f) ? c2 : 1e-6f;
            float rcc = __frcp_rn(zsc);
            float uc = __fmul_rn(uwc, rcc), vc = __fmul_rn(vwc, rcc);
            float ud = __fmul_rn(uwd, rcc), vd = __fmul_rn(vwd, rcc);

            bool validc = (uc >= 0.f) && (uc <= (float)(FWw - 1)) &&
                          (vc >= 0.f) && (vc <= (float)(FHh - 1));
            bool validd = (ud >= 0.f) && (ud <= (float)(DWw - 1)) &&
                          (vd >= 0.f) && (vd <= (float)(DHh - 1));

            // nearest depth sample (rintf == round-half-even == jnp.round)
            int xi = (int)fminf(fmaxf(rintf(ud), 0.f), (float)(DWw - 1));
            int yi = (int)fminf(fmaxf(rintf(vd), 0.f), (float)(DHh - 1));
            float dep = pred_depth[(v * DHh + yi) * DWw + xi];

            bool valid = validc && validd && (c2 > 0.f) && (dep > 0.f);
            float dist = fabsf(__fadd_rn(c2, -dep));
            float t16 = __fmul_rn(dist, 16.0f);
            float w = __fmul_rn(expf(-__fmul_rn(t16, t16)), (valid ? 1.0f : 0.0f));

            // bilinear setup (clipped coords)
            float u  = fminf(fmaxf(uc, 0.f), (float)(FWw - 1));
            float vv = fminf(fmaxf(vc, 0.f), (float)(FHh - 1));
            float x0f = floorf(u), y0f = floorf(vv);
            int x0 = (int)x0f, y0 = (int)y0f;
            int dx = (x0 < FWw - 1) ? 1 : 0;
            int dy = (y0 < FHh - 1) ? 1 : 0;
            int bp = v * HW + y0 * FWw + x0;
            int bits = (bp << 3) | (dx << 2) | (dy << 1) | (valid ? 1 : 0);
            pv = make_float4(w, __fadd_rn(u, -x0f), __fadd_rn(vv, -y0f), __int_as_float(bits));
            if (w != 0.f) atomicOr(&s_mask[p], 1 << v);   // order-independent
        }
        s_pv[item] = pv;   // item == p*8 + v
    }
    __syncthreads();

    // ---------------- Phase B: TWO points per warp, mask-compacted ----------
    // lanes 0-11 handle even point, lanes 16-27 handle odd point. Each half
    // walks its own active-view mask ascending (same order => bit-exact).
    // Halves run in lockstep by iteration index; trips = max(cntA, cntB).
    {
        int warp = tid >> 5, lane = tid & 31;
        int sub = lane >> 4;          // 0 or 1
        int l   = lane & 15;          // 0..15
        int lc  = (l < 12) ? l : 11;  // clamp: lanes 12-15 mirror lane 11 (same sector)
        bool ch_act = (l < 12);
        for (int pp = warp; pp < PB / 2; pp += NWARPS) {
            int p = pp * 2 + sub;
            float4 acc = make_float4(0.f, 0.f, 0.f, 0.f);
            int mask = s_mask[p];
            while (mask) {
                int v = __ffs(mask) - 1;
                mask &= mask - 1;
                float4 pv = s_pv[p * 8 + v];
                int bits = __float_as_int(pv.w);
                int bp  = bits >> 3;
                int o01 = ((bits >> 2) & 1) * 12;
                int o10 = ((bits >> 1) & 1) * (FWw * 12);
                const float4* fptr = reinterpret_cast<const float4*>(g_feats_t) + (size_t)bp * 12;
                float4 a = fptr[lc];
                float4 b = fptr[o01 + lc];
                float4 c = fptr[o10 + lc];
                float4 d = fptr[o01 + o10 + lc];
                float wx = pv.y, wy = pv.z;
                float owx = __fadd_rn(1.f, -wx);
                float owy = __fadd_rn(1.f, -wy);
                float w = pv.x;
#define BILIN(FLD)                                                          \
                {                                                           \
                    float t0 = __fmul_rn(__fmul_rn(a.FLD, owy), owx);       \
                    float t1 = __fmul_rn(__fmul_rn(b.FLD, owy), wx);        \
                    float t2 = __fmul_rn(__fmul_rn(c.FLD, wy),  owx);       \
                    float t3 = __fmul_rn(__fmul_rn(d.FLD, wy),  wx);        \
                    float s  = __fadd_rn(__fadd_rn(__fadd_rn(t0, t1), t2), t3); \
                    acc.FLD  = __fadd_rn(acc.FLD, __fmul_rn(s, w));         \
                }
                BILIN(x) BILIN(y) BILIN(z) BILIN(w)
#undef BILIN
            }
            if (ch_act)
                reinterpret_cast<float4*>(s_dens)[p * 12 + l] = acc;
        }
    }
    __syncthreads();

    // ---------------- Phase C: coalesced output ----------------
    float* dens_out = out;
    float* ws_out   = out + (size_t)CC * NPTS;
    float* cnt_out  = out + (size_t)CC * NPTS + NPTS;

    if (tid < PB) {
        int p = tid, n = base + p;
        if (n < NPTS) {
            float ws = 0.f, ct = 0.f;
#pragma unroll
            for (int v = 0; v < BV; v++) {
                float4 pv = s_pv[p * 8 + v];
                ws = __fadd_rn(ws, pv.x);
                ct = __fadd_rn(ct, (float)(__float_as_int(pv.w) & 1));
            }
            ws_out[n]  = ws;
            cnt_out[n] = ct;
        }
    }
    for (int i = tid; i < CC * PB; i += THREADS) {
        int c = i >> 7;          // PB == 128
        int p = i & (PB - 1);
        int n = base + p;
        if (n < NPTS) dens_out[(size_t)c * NPTS + n] = s_dens[p * CP + c];
    }
}

// ---------------------------------------------------------------------------
extern "C" void kernel_launch(void* const* d_in, const int* in_sizes, int n_in,
                              void* d_out, int out_size) {
    const float* img_feats  = (const float*)d_in[0];
    const float* pred_depth = (const float*)d_in[1];
    const float* poses      = (const float*)d_in[2];
    const float* Kc         = (const float*)d_in[3];
    const float* Kd         = (const float*)d_in[4];
    const float* coords     = (const float*)d_in[5];
    float* out = (float*)d_out;

    prep_kernel<<<(BV * HW + 255) / 256, 256>>>(img_feats, poses);
    int blocks = (NPTS + PB - 1) / PB;
    fuse_kernel<<<blocks, THREADS>>>(pred_depth, Kc, Kd, coords, out);
}